// round 1
// baseline (speedup 1.0000x reference)
#include <cuda_runtime.h>

// ComplexDotProductAttention: B=4, Q=K=4096, D=V=64, complex fp32 (last dim = re/im).
//
// S_r = (Qr Kr^T + Qi Ki^T) * s ; S_i = (Qr Ki^T - Qi Kr^T) * s ; s = 1/sqrt(D)
// n = |S| ; change = softmax_k(n) / (n + eps)
// Y = (S * change) . V   (complex matmul)
//
// Flash-style single pass over K with online max/denominator.
// weight per element = exp(n - m) * rsqrt(s2)   (1/(n+eps) ~= 1/n, eps=1e-9 negligible)

#define NB    4
#define QLEN  4096
#define KLEN  4096
#define DH    64
#define VH    64
#define TQ    64
#define TK    64
#define PAD   66      // smem row stride in float2 (16B-aligned rows, bank-friendly)

__global__ __launch_bounds__(256, 2)
void cdpa_kernel(const float* __restrict__ gq,
                 const float* __restrict__ gk,
                 const float* __restrict__ gv,
                 float* __restrict__ gout)
{
    extern __shared__ float smem_raw[];
    float2* sQ  = (float2*)smem_raw;      // [TQ][PAD]  (q-major, d across; scaled)
    float2* sKT = sQ  + TQ * PAD;         // [DH][PAD]  (d-major, k across); reused as sA[TQ][PAD]
    float2* sV  = sKT + DH * PAD;         // [TK][PAD]  (k-major, v across)

    const int b   = blockIdx.y;
    const int q0  = blockIdx.x * TQ;
    const int tid = threadIdx.x;
    const int tx  = tid & 15;             // k / v group
    const int ty  = tid >> 4;             // q group
    const int qq  = ty * 4;               // local q base (4 rows)
    const int kk0 = tx * 4;               // local k (and v) base (4 cols)

    const float scale = 0.125f;           // 1/sqrt(64)

    // ---- load Q tile once, fold in scale ----
    {
        const float4* g = (const float4*)gq + (size_t)(b * QLEN + q0) * (DH * 2 / 4);
        float4* s4 = (float4*)sQ;         // row stride PAD/2 = 33 float4
        #pragma unroll
        for (int i = 0; i < 8; ++i) {
            int e = i * 256 + tid;        // 0..2047 float4s
            int row = e >> 5, col = e & 31;
            float4 val = g[e];
            val.x *= scale; val.y *= scale; val.z *= scale; val.w *= scale;
            s4[row * (PAD / 2) + col] = val;
        }
    }

    float m[4], Z[4], Yr[4][4], Yi[4][4], nrm[4][4];
    #pragma unroll
    for (int i = 0; i < 4; ++i) {
        m[i] = -1e30f;
        Z[i] = 0.0f;
        #pragma unroll
        for (int j = 0; j < 4; ++j) { Yr[i][j] = 0.0f; Yi[i][j] = 0.0f; }
    }

    const size_t kvbase4 = (size_t)(b) * KLEN * (DH * 2 / 4);

    for (int kt = 0; kt < KLEN; kt += TK) {
        __syncthreads();  // prior-iter reads of sKT(A)/sV complete before overwrite

        // ---- load K tile transposed: sKT[d][k] ----
        {
            const float4* g = (const float4*)gk + kvbase4 + (size_t)kt * 32;
            #pragma unroll
            for (int i = 0; i < 8; ++i) {
                int e = i * 256 + tid;
                int krow = e >> 5, dp = e & 31;
                float4 val = g[e];
                sKT[(2 * dp    ) * PAD + krow] = make_float2(val.x, val.y);
                sKT[(2 * dp + 1) * PAD + krow] = make_float2(val.z, val.w);
            }
        }
        // ---- load V tile straight: sV[k][v] ----
        {
            const float4* g = (const float4*)gv + kvbase4 + (size_t)kt * 32;
            float4* s4 = (float4*)sV;
            #pragma unroll
            for (int i = 0; i < 8; ++i) {
                int e = i * 256 + tid;
                int row = e >> 5, col = e & 31;
                s4[row * (PAD / 2) + col] = g[e];
            }
        }
        __syncthreads();

        // ---- S gemm: Sr/Si[4q][4k] over D=64 (2 d's per step) ----
        float Sr[4][4] = {}, Si[4][4] = {};
        #pragma unroll 4
        for (int dp = 0; dp < 32; ++dp) {
            const int d = dp * 2;
            float4 qf[4];
            #pragma unroll
            for (int i = 0; i < 4; ++i)
                qf[i] = *(const float4*)&sQ[(qq + i) * PAD + d];   // (Qr_d,Qi_d,Qr_d1,Qi_d1)
            const float4 ka = *(const float4*)&sKT[d * PAD + kk0];          // k0,k1 @ d
            const float4 kb = *(const float4*)&sKT[d * PAD + kk0 + 2];      // k2,k3 @ d
            const float4 kc = *(const float4*)&sKT[(d + 1) * PAD + kk0];    // k0,k1 @ d+1
            const float4 kd = *(const float4*)&sKT[(d + 1) * PAD + kk0 + 2];// k2,k3 @ d+1
            #pragma unroll
            for (int i = 0; i < 4; ++i) {
                float Qr = qf[i].x, Qi = qf[i].y;
                Sr[i][0] += Qr * ka.x + Qi * ka.y;  Si[i][0] += Qr * ka.y - Qi * ka.x;
                Sr[i][1] += Qr * ka.z + Qi * ka.w;  Si[i][1] += Qr * ka.w - Qi * ka.z;
                Sr[i][2] += Qr * kb.x + Qi * kb.y;  Si[i][2] += Qr * kb.y - Qi * kb.x;
                Sr[i][3] += Qr * kb.z + Qi * kb.w;  Si[i][3] += Qr * kb.w - Qi * kb.z;
                Qr = qf[i].z; Qi = qf[i].w;
                Sr[i][0] += Qr * kc.x + Qi * kc.y;  Si[i][0] += Qr * kc.y - Qi * kc.x;
                Sr[i][1] += Qr * kc.z + Qi * kc.w;  Si[i][1] += Qr * kc.w - Qi * kc.z;
                Sr[i][2] += Qr * kd.x + Qi * kd.y;  Si[i][2] += Qr * kd.y - Qi * kd.x;
                Sr[i][3] += Qr * kd.z + Qi * kd.w;  Si[i][3] += Qr * kd.w - Qi * kd.z;
            }
        }

        // ---- norms; fold rsqrt into S (unit direction) ----
        #pragma unroll
        for (int i = 0; i < 4; ++i) {
            #pragma unroll
            for (int j = 0; j < 4; ++j) {
                float s2 = Sr[i][j] * Sr[i][j] + Si[i][j] * Si[i][j];
                float r = rsqrtf(s2);
                float n = s2 * r;
                if (s2 < 1e-35f) { r = 0.0f; n = 0.0f; }
                nrm[i][j] = n;
                Sr[i][j] *= r;
                Si[i][j] *= r;
            }
        }

        // ---- online softmax update (per q row, across 16 tx lanes) ----
        #pragma unroll
        for (int i = 0; i < 4; ++i) {
            float tmax = fmaxf(fmaxf(nrm[i][0], nrm[i][1]), fmaxf(nrm[i][2], nrm[i][3]));
            #pragma unroll
            for (int o = 8; o >= 1; o >>= 1)
                tmax = fmaxf(tmax, __shfl_xor_sync(0xffffffffu, tmax, o, 16));
            float mn = fmaxf(m[i], tmax);
            float alpha = __expf(m[i] - mn);
            m[i] = mn;
            Z[i] *= alpha;
            #pragma unroll
            for (int j = 0; j < 4; ++j) { Yr[i][j] *= alpha; Yi[i][j] *= alpha; }
            float esum = 0.0f;
            #pragma unroll
            for (int j = 0; j < 4; ++j) {
                float e = __expf(nrm[i][j] - mn);
                nrm[i][j] = e;              // keep e for the A-write
                esum += e;
            }
            #pragma unroll
            for (int o = 8; o >= 1; o >>= 1)
                esum += __shfl_xor_sync(0xffffffffu, esum, o, 16);
            Z[i] += esum;
        }

        __syncthreads();   // all S-gemm reads of sKT done before overwriting with A
        {
            float2* sA = sKT;   // reuse: sA[q][k], stride PAD
            #pragma unroll
            for (int i = 0; i < 4; ++i)
                #pragma unroll
                for (int j = 0; j < 4; ++j)
                    sA[(qq + i) * PAD + kk0 + j] =
                        make_float2(Sr[i][j] * nrm[i][j], Si[i][j] * nrm[i][j]);
        }
        __syncthreads();

        // ---- Y += A . V (complex) ----
        const float2* sA = sKT;
        #pragma unroll 4
        for (int kk = 0; kk < TK; ++kk) {
            float2 a[4];
            #pragma unroll
            for (int i = 0; i < 4; ++i) a[i] = sA[(qq + i) * PAD + kk];
            const float4 v0 = *(const float4*)&sV[kk * PAD + kk0];      // v0,v1
            const float4 v1 = *(const float4*)&sV[kk * PAD + kk0 + 2];  // v2,v3
            #pragma unroll
            for (int i = 0; i < 4; ++i) {
                const float Ar = a[i].x, Ai = a[i].y;
                Yr[i][0] += Ar * v0.x - Ai * v0.y;  Yi[i][0] += Ar * v0.y + Ai * v0.x;
                Yr[i][1] += Ar * v0.z - Ai * v0.w;  Yi[i][1] += Ar * v0.w + Ai * v0.z;
                Yr[i][2] += Ar * v1.x - Ai * v1.y;  Yi[i][2] += Ar * v1.y + Ai * v1.x;
                Yr[i][3] += Ar * v1.z - Ai * v1.w;  Yi[i][3] += Ar * v1.w + Ai * v1.z;
            }
        }
    }

    // ---- epilogue: divide by softmax denominator, write [B,Q,V,2] ----
    float2* o = (float2*)gout + (size_t)(b * QLEN + q0) * VH;
    #pragma unroll
    for (int i = 0; i < 4; ++i) {
        const float inv = 1.0f / Z[i];
        #pragma unroll
        for (int j = 0; j < 4; ++j)
            o[(qq + i) * VH + kk0 + j] =
                make_float2(Yr[i][j] * inv, Yi[i][j] * inv);
    }
}

extern "C" void kernel_launch(void* const* d_in, const int* in_sizes, int n_in,
                              void* d_out, int out_size)
{
    const float* q = (const float*)d_in[0];
    const float* k = (const float*)d_in[1];
    const float* v = (const float*)d_in[2];
    float* out = (float*)d_out;

    const size_t smem = (size_t)3 * TQ * PAD * sizeof(float2);  // 101376 B
    cudaFuncSetAttribute(cdpa_kernel,
                         cudaFuncAttributeMaxDynamicSharedMemorySize, (int)smem);
    dim3 grid(QLEN / TQ, NB);
    cdpa_kernel<<<grid, 256, smem>>>(q, k, v, out);
}

// round 2
// speedup vs baseline: 1.8247x; 1.8247x over previous
#include <cuda_runtime.h>

// ComplexDotProductAttention on GB300 (sm_103a): B=4, Q=K=4096, D=V=64, complex fp32.
// Flash-style single pass over K; inner GEMMs use packed fma.rn.f32x2 (FFMA2):
//   S:  acc1 += (Qr,Qr)*(Kr,Ki); acc2 += (Qi,Qi)*(Kr,Ki)
//       Sr = acc1.lo + acc2.hi ; Si = acc1.hi - acc2.lo
//   AV: Y1 += (Ar,Ar)*(Vr,Vi);  Y2 += (Ai,Ai)*(Vr,Vi)
//       Yr = Y1.lo - Y2.hi ; Yi = Y1.hi + Y2.lo

#define NB      4
#define QLEN    4096
#define KLEN    4096
#define DH      64
#define VH      64
#define TQ      64
#define TK      64
#define QSTRIDE 65   // sQ row stride in float4 (pad to dodge bank conflicts)
#define KSTRIDE 66   // sKT/sV/sA row stride in float2

#define FFMA2(acc, a, b) \
    asm("fma.rn.f32x2 %0, %1, %2, %0;" : "+l"(acc) : "l"(a), "l"(b))

__device__ __forceinline__ float lo32(unsigned long long v) {
    return __uint_as_float((unsigned)v);
}
__device__ __forceinline__ float hi32(unsigned long long v) {
    return __uint_as_float((unsigned)(v >> 32));
}
__device__ __forceinline__ unsigned long long dup2(float x) {
    unsigned long long r;
    asm("mov.b64 %0, {%1, %1};" : "=l"(r) : "f"(x));
    return r;
}
__device__ __forceinline__ unsigned long long mul2(unsigned long long a,
                                                   unsigned long long b) {
    unsigned long long r;
    asm("mul.rn.f32x2 %0, %1, %2;" : "=l"(r) : "l"(a), "l"(b));
    return r;
}

__global__ __launch_bounds__(256, 1)
void cdpa_kernel(const float* __restrict__ gq,
                 const float* __restrict__ gk,
                 const float* __restrict__ gv,
                 float* __restrict__ gout)
{
    extern __shared__ char smem_raw[];
    float4* sQ  = (float4*)smem_raw;                               // [TQ][QSTRIDE] dup: (Qr,Qr,Qi,Qi), scaled
    float2* sKT = (float2*)(smem_raw + TQ * QSTRIDE * sizeof(float4)); // [DH][KSTRIDE] (Kr,Ki), k across
    float2* sV  = sKT + DH * KSTRIDE;                              // [TK][KSTRIDE] (Vr,Vi), v across
    float2* sA  = sV  + TK * KSTRIDE;                              // [TQ][KSTRIDE] (Ar,Ai)

    const int b   = blockIdx.y;
    const int q0  = blockIdx.x * TQ;
    const int tid = threadIdx.x;
    const int tx  = tid & 15;             // k / v group (16 lanes cover 64 cols)
    const int ty  = tid >> 4;             // q group
    const int qq  = ty * 4;               // local q base (4 rows)
    const int kk0 = tx * 4;               // local k (and v) base (4 cols)

    const float scale = 0.125f;           // 1/sqrt(64)

    // ---- load Q tile once, duplicated layout, fold in scale ----
    {
        const float4* g = (const float4*)gq + (size_t)(b * QLEN + q0) * (DH * 2 / 4);
        #pragma unroll
        for (int i = 0; i < 8; ++i) {
            int e = i * 256 + tid;        // 0..2047 float4s
            int row = e >> 5, dp = e & 31;
            float4 v = g[e];              // (Qr_d, Qi_d, Qr_d1, Qi_d1)
            sQ[row * QSTRIDE + 2 * dp    ] = make_float4(v.x * scale, v.x * scale,
                                                         v.y * scale, v.y * scale);
            sQ[row * QSTRIDE + 2 * dp + 1] = make_float4(v.z * scale, v.z * scale,
                                                         v.w * scale, v.w * scale);
        }
    }

    float m[4], Z[4], nrm[4][4];
    unsigned long long Y1[4][4], Y2[4][4];
    #pragma unroll
    for (int i = 0; i < 4; ++i) {
        m[i] = -1e30f;
        Z[i] = 0.0f;
        #pragma unroll
        for (int j = 0; j < 4; ++j) { Y1[i][j] = 0ull; Y2[i][j] = 0ull; }
    }

    const size_t kvbase4 = (size_t)(b) * KLEN * (DH * 2 / 4);

    for (int kt = 0; kt < KLEN; kt += TK) {
        __syncthreads();  // prior-iter reads of sKT/sV complete before overwrite

        // ---- load K tile transposed: sKT[d][k] = (Kr,Ki) ----
        {
            const float4* g = (const float4*)gk + kvbase4 + (size_t)kt * 32;
            #pragma unroll
            for (int i = 0; i < 8; ++i) {
                int e = i * 256 + tid;
                int krow = e >> 5, dp = e & 31;
                float4 v = g[e];
                sKT[(2 * dp    ) * KSTRIDE + krow] = make_float2(v.x, v.y);
                sKT[(2 * dp + 1) * KSTRIDE + krow] = make_float2(v.z, v.w);
            }
        }
        // ---- load V tile straight: sV[k][v] = (Vr,Vi) ----
        {
            const float4* g = (const float4*)gv + kvbase4 + (size_t)kt * 32;
            #pragma unroll
            for (int i = 0; i < 8; ++i) {
                int e = i * 256 + tid;
                int row = e >> 5, col = e & 31;
                *(float4*)&sV[row * KSTRIDE + col * 2] = g[e];
            }
        }
        __syncthreads();

        // ---- S gemm via packed FFMA2 ----
        unsigned long long acc1[4][4], acc2[4][4];
        #pragma unroll
        for (int i = 0; i < 4; ++i)
            #pragma unroll
            for (int j = 0; j < 4; ++j) { acc1[i][j] = 0ull; acc2[i][j] = 0ull; }

        #pragma unroll 2
        for (int d = 0; d < DH; ++d) {
            ulonglong2 qv[4];
            #pragma unroll
            for (int i = 0; i < 4; ++i)
                qv[i] = *(const ulonglong2*)(sQ + (qq + i) * QSTRIDE + d); // .x=(Qr,Qr) .y=(Qi,Qi)
            const ulonglong2 kv0 = *(const ulonglong2*)(sKT + d * KSTRIDE + kk0);     // k0,k1
            const ulonglong2 kv1 = *(const ulonglong2*)(sKT + d * KSTRIDE + kk0 + 2); // k2,k3
            #pragma unroll
            for (int i = 0; i < 4; ++i) {
                FFMA2(acc1[i][0], qv[i].x, kv0.x);  FFMA2(acc2[i][0], qv[i].y, kv0.x);
                FFMA2(acc1[i][1], qv[i].x, kv0.y);  FFMA2(acc2[i][1], qv[i].y, kv0.y);
                FFMA2(acc1[i][2], qv[i].x, kv1.x);  FFMA2(acc2[i][2], qv[i].y, kv1.x);
                FFMA2(acc1[i][3], qv[i].x, kv1.y);  FFMA2(acc2[i][3], qv[i].y, kv1.y);
            }
        }

        // ---- unpack, norms; fold rsqrt into S (unit direction) ----
        float Sr[4][4], Si[4][4];
        #pragma unroll
        for (int i = 0; i < 4; ++i) {
            #pragma unroll
            for (int j = 0; j < 4; ++j) {
                float sr = lo32(acc1[i][j]) + hi32(acc2[i][j]);
                float si = hi32(acc1[i][j]) - lo32(acc2[i][j]);
                float s2 = sr * sr + si * si;
                float r = rsqrtf(s2);
                float n = s2 * r;
                if (s2 < 1e-35f) { r = 0.0f; n = 0.0f; }
                nrm[i][j] = n;
                Sr[i][j] = sr * r;
                Si[i][j] = si * r;
            }
        }

        // ---- online softmax update (per q row, across 16 tx lanes) ----
        #pragma unroll
        for (int i = 0; i < 4; ++i) {
            float tmax = fmaxf(fmaxf(nrm[i][0], nrm[i][1]), fmaxf(nrm[i][2], nrm[i][3]));
            #pragma unroll
            for (int o = 8; o >= 1; o >>= 1)
                tmax = fmaxf(tmax, __shfl_xor_sync(0xffffffffu, tmax, o, 16));
            float mn = fmaxf(m[i], tmax);
            float alpha = __expf(m[i] - mn);
            m[i] = mn;
            Z[i] *= alpha;
            const unsigned long long ap = dup2(alpha);
            #pragma unroll
            for (int j = 0; j < 4; ++j) {
                Y1[i][j] = mul2(Y1[i][j], ap);
                Y2[i][j] = mul2(Y2[i][j], ap);
            }
            float esum = 0.0f;
            #pragma unroll
            for (int j = 0; j < 4; ++j) {
                float e = __expf(nrm[i][j] - mn);
                nrm[i][j] = e;              // keep e for the A-write
                esum += e;
            }
            #pragma unroll
            for (int o = 8; o >= 1; o >>= 1)
                esum += __shfl_xor_sync(0xffffffffu, esum, o, 16);
            Z[i] += esum;
        }

        // ---- write A = (unit-S) * e ----
        #pragma unroll
        for (int i = 0; i < 4; ++i)
            #pragma unroll
            for (int j = 0; j < 4; ++j)
                sA[(qq + i) * KSTRIDE + kk0 + j] =
                    make_float2(Sr[i][j] * nrm[i][j], Si[i][j] * nrm[i][j]);
        __syncthreads();

        // ---- Y += A . V via packed FFMA2 ----
        #pragma unroll 2
        for (int kk = 0; kk < TK; ++kk) {
            float2 a[4];
            #pragma unroll
            for (int i = 0; i < 4; ++i) a[i] = sA[(qq + i) * KSTRIDE + kk];
            const ulonglong2 v0 = *(const ulonglong2*)(sV + kk * KSTRIDE + kk0);     // v0,v1
            const ulonglong2 v1 = *(const ulonglong2*)(sV + kk * KSTRIDE + kk0 + 2); // v2,v3
            #pragma unroll
            for (int i = 0; i < 4; ++i) {
                const unsigned long long ar = dup2(a[i].x);
                const unsigned long long ai = dup2(a[i].y);
                FFMA2(Y1[i][0], ar, v0.x);  FFMA2(Y2[i][0], ai, v0.x);
                FFMA2(Y1[i][1], ar, v0.y);  FFMA2(Y2[i][1], ai, v0.y);
                FFMA2(Y1[i][2], ar, v1.x);  FFMA2(Y2[i][2], ai, v1.x);
                FFMA2(Y1[i][3], ar, v1.y);  FFMA2(Y2[i][3], ai, v1.y);
            }
        }
    }

    // ---- epilogue: combine lanes, divide by denominator, write [B,Q,V,2] ----
    float2* o = (float2*)gout + (size_t)(b * QLEN + q0) * VH;
    #pragma unroll
    for (int i = 0; i < 4; ++i) {
        const float inv = 1.0f / Z[i];
        #pragma unroll
        for (int j = 0; j < 4; ++j) {
            float yr = lo32(Y1[i][j]) - hi32(Y2[i][j]);
            float yi = hi32(Y1[i][j]) + lo32(Y2[i][j]);
            o[(qq + i) * VH + kk0 + j] = make_float2(yr * inv, yi * inv);
        }
    }
}

extern "C" void kernel_launch(void* const* d_in, const int* in_sizes, int n_in,
                              void* d_out, int out_size)
{
    const float* q = (const float*)d_in[0];
    const float* k = (const float*)d_in[1];
    const float* v = (const float*)d_in[2];
    float* out = (float*)d_out;

    const size_t smem = (size_t)TQ * QSTRIDE * sizeof(float4)
                      + (size_t)3 * TK * KSTRIDE * sizeof(float2);  // 167,936 B
    cudaFuncSetAttribute(cdpa_kernel,
                         cudaFuncAttributeMaxDynamicSharedMemorySize, (int)smem);
    dim3 grid(QLEN / TQ, NB);
    cdpa_kernel<<<grid, 256, smem>>>(q, k, v, out);
}

// round 3
// speedup vs baseline: 1.9033x; 1.0431x over previous
#include <cuda_runtime.h>

// ComplexDotProductAttention on GB300 (sm_103a): B=4, Q=K=4096, D=V=64, complex fp32.
// Flash-style single pass over K. All smem tiles natural (re,im) float2.
// Packed fma.rn.f32x2 with register-side swap of the shared operand:
//   S:  acc_s += (Qr,Qi)*(Kr,Ki) -> Sr = lo+hi ; acc_d += (Qr,Qi)*(Ki,Kr) -> Si = lo-hi
//   AV: P += (Ar,Ai)*(Vr,Vi) -> Yr = lo-hi    ; Qc += (Ar,Ai)*(Vi,Vr) -> Yi = lo+hi
// Thread k/v columns {2tx, 2tx+1, 2tx+32, 2tx+33} so K/V/A LDS.128 hit
// consecutive 16B units across lanes (conflict-free).

#define NB      4
#define QLEN    4096
#define KLEN    4096
#define DH      64
#define VH      64
#define TQ      64
#define TK      64
#define QS      66   // sQ row stride in float2
#define KS      66   // sKT/sV/sA row stride in float2

#define FFMA2(acc, a, b) \
    asm("fma.rn.f32x2 %0, %1, %2, %0;" : "+l"(acc) : "l"(a), "l"(b))

typedef unsigned long long u64;

__device__ __forceinline__ float lo32(u64 v) { return __uint_as_float((unsigned)v); }
__device__ __forceinline__ float hi32(u64 v) { return __uint_as_float((unsigned)(v >> 32)); }
__device__ __forceinline__ u64 pk2(float lo, float hi) {
    u64 r; asm("mov.b64 %0, {%1, %2};" : "=l"(r) : "f"(lo), "f"(hi)); return r;
}
__device__ __forceinline__ u64 swp(u64 v) { return pk2(hi32(v), lo32(v)); }
__device__ __forceinline__ u64 dup2(float x) {
    u64 r; asm("mov.b64 %0, {%1, %1};" : "=l"(r) : "f"(x)); return r;
}
__device__ __forceinline__ u64 mul2(u64 a, u64 b) {
    u64 r; asm("mul.rn.f32x2 %0, %1, %2;" : "=l"(r) : "l"(a), "l"(b)); return r;
}

__global__ __launch_bounds__(256, 1)
void cdpa_kernel(const float* __restrict__ gq,
                 const float* __restrict__ gk,
                 const float* __restrict__ gv,
                 float* __restrict__ gout)
{
    extern __shared__ char smem_raw[];
    float2* sQ  = (float2*)smem_raw;       // [TQ][QS]  (Qr,Qi), scaled
    float2* sKT = sQ  + TQ * QS;           // [DH][KS]  (Kr,Ki), k across
    float2* sV  = sKT + DH * KS;           // [TK][KS]  (Vr,Vi), v across
    float2* sA  = sV  + TK * KS;           // [TQ][KS]  (Ar,Ai)

    const int b   = blockIdx.y;
    const int q0  = blockIdx.x * TQ;
    const int tid = threadIdx.x;
    const int tx  = tid & 15;              // k / v group
    const int ty  = tid >> 4;              // q group
    const int qq  = ty * 4;                // local q base (4 rows)
    const int c0  = 2 * tx;                // k/v cols: c0, c0+1, c0+32, c0+33

    const float scale = 0.125f;            // 1/sqrt(64)

    // ---- load Q tile once (natural layout), fold in scale ----
    {
        const float4* g = (const float4*)gq + (size_t)(b * QLEN + q0) * (DH * 2 / 4);
        #pragma unroll
        for (int i = 0; i < 8; ++i) {
            int e = i * 256 + tid;         // 0..2047 float4s
            int row = e >> 5, dp = e & 31; // dp indexes pairs of d
            float4 v = g[e];               // (Qr_d, Qi_d, Qr_d1, Qi_d1)
            sQ[row * QS + 2 * dp    ] = make_float2(v.x * scale, v.y * scale);
            sQ[row * QS + 2 * dp + 1] = make_float2(v.z * scale, v.w * scale);
        }
    }

    float m[4], Z[4], nrm[4][4];
    u64 P[4][4], Qc[4][4];
    #pragma unroll
    for (int i = 0; i < 4; ++i) {
        m[i] = -1e30f;
        Z[i] = 0.0f;
        #pragma unroll
        for (int j = 0; j < 4; ++j) { P[i][j] = 0ull; Qc[i][j] = 0ull; }
    }

    const size_t kvbase4 = (size_t)(b) * KLEN * (DH * 2 / 4);

    for (int kt = 0; kt < KLEN; kt += TK) {
        __syncthreads();  // prior-iter reads of sKT/sV/sA complete before overwrite

        // ---- load K tile transposed: sKT[d][k] = (Kr,Ki) ----
        {
            const float4* g = (const float4*)gk + kvbase4 + (size_t)kt * 32;
            #pragma unroll
            for (int i = 0; i < 8; ++i) {
                int e = i * 256 + tid;
                int krow = e >> 5, dp = e & 31;
                float4 v = g[e];
                sKT[(2 * dp    ) * KS + krow] = make_float2(v.x, v.y);
                sKT[(2 * dp + 1) * KS + krow] = make_float2(v.z, v.w);
            }
        }
        // ---- load V tile straight: sV[k][v] = (Vr,Vi) ----
        {
            const float4* g = (const float4*)gv + kvbase4 + (size_t)kt * 32;
            #pragma unroll
            for (int i = 0; i < 8; ++i) {
                int e = i * 256 + tid;
                int row = e >> 5, col = e & 31;
                *(float4*)&sV[row * KS + col * 2] = g[e];
            }
        }
        __syncthreads();

        // ---- S gemm: packed FFMA2, natural layouts ----
        u64 accS[4][4], accD[4][4];
        #pragma unroll
        for (int i = 0; i < 4; ++i)
            #pragma unroll
            for (int j = 0; j < 4; ++j) { accS[i][j] = 0ull; accD[i][j] = 0ull; }

        #pragma unroll 2
        for (int d = 0; d < DH; d += 2) {
            ulonglong2 qv[4];              // .x = Q pair @ d, .y = @ d+1
            #pragma unroll
            for (int i = 0; i < 4; ++i)
                qv[i] = *(const ulonglong2*)(sQ + (qq + i) * QS + d);
            // K: units tx and tx+16 of rows d, d+1 (consecutive across lanes)
            const ulonglong2 kA = *(const ulonglong2*)(sKT + d * KS + c0);           // k c0,c0+1 @ d
            const ulonglong2 kB = *(const ulonglong2*)(sKT + d * KS + c0 + 32);      // k c0+32,+33 @ d
            const ulonglong2 kC = *(const ulonglong2*)(sKT + (d + 1) * KS + c0);     // @ d+1
            const ulonglong2 kD = *(const ulonglong2*)(sKT + (d + 1) * KS + c0 + 32);
            const u64 k0 = kA.x, k1 = kA.y, k2 = kB.x, k3 = kB.y;
            const u64 s0 = swp(k0), s1 = swp(k1), s2 = swp(k2), s3 = swp(k3);
            const u64 k4 = kC.x, k5 = kC.y, k6 = kD.x, k7 = kD.y;
            const u64 s4 = swp(k4), s5 = swp(k5), s6 = swp(k6), s7 = swp(k7);
            #pragma unroll
            for (int i = 0; i < 4; ++i) {
                const u64 qa = qv[i].x;    // @ d
                FFMA2(accS[i][0], qa, k0);  FFMA2(accD[i][0], qa, s0);
                FFMA2(accS[i][1], qa, k1);  FFMA2(accD[i][1], qa, s1);
                FFMA2(accS[i][2], qa, k2);  FFMA2(accD[i][2], qa, s2);
                FFMA2(accS[i][3], qa, k3);  FFMA2(accD[i][3], qa, s3);
                const u64 qb = qv[i].y;    // @ d+1
                FFMA2(accS[i][0], qb, k4);  FFMA2(accD[i][0], qb, s4);
                FFMA2(accS[i][1], qb, k5);  FFMA2(accD[i][1], qb, s5);
                FFMA2(accS[i][2], qb, k6);  FFMA2(accD[i][2], qb, s6);
                FFMA2(accS[i][3], qb, k7);  FFMA2(accD[i][3], qb, s7);
            }
        }

        // ---- unpack, norms; fold rsqrt into S (unit direction) ----
        float Sr[4][4], Si[4][4];
        #pragma unroll
        for (int i = 0; i < 4; ++i) {
            #pragma unroll
            for (int j = 0; j < 4; ++j) {
                float sr = lo32(accS[i][j]) + hi32(accS[i][j]);
                float si = lo32(accD[i][j]) - hi32(accD[i][j]);
                float s2v = sr * sr + si * si;
                float r = rsqrtf(s2v);
                float n = s2v * r;
                if (s2v < 1e-35f) { r = 0.0f; n = 0.0f; }
                nrm[i][j] = n;
                Sr[i][j] = sr * r;
                Si[i][j] = si * r;
            }
        }

        // ---- online softmax update (per q row, across 16 tx lanes) ----
        #pragma unroll
        for (int i = 0; i < 4; ++i) {
            float tmax = fmaxf(fmaxf(nrm[i][0], nrm[i][1]), fmaxf(nrm[i][2], nrm[i][3]));
            #pragma unroll
            for (int o = 8; o >= 1; o >>= 1)
                tmax = fmaxf(tmax, __shfl_xor_sync(0xffffffffu, tmax, o, 16));
            float mn = fmaxf(m[i], tmax);
            float alpha = __expf(m[i] - mn);
            m[i] = mn;
            Z[i] *= alpha;
            const u64 ap = dup2(alpha);
            #pragma unroll
            for (int j = 0; j < 4; ++j) {
                P[i][j]  = mul2(P[i][j],  ap);
                Qc[i][j] = mul2(Qc[i][j], ap);
            }
            float esum = 0.0f;
            #pragma unroll
            for (int j = 0; j < 4; ++j) {
                float e = __expf(nrm[i][j] - mn);
                nrm[i][j] = e;
                esum += e;
            }
            #pragma unroll
            for (int o = 8; o >= 1; o >>= 1)
                esum += __shfl_xor_sync(0xffffffffu, esum, o, 16);
            Z[i] += esum;
        }

        // ---- write A: cols {c0, c0+1} and {c0+32, c0+33} ----
        #pragma unroll
        for (int i = 0; i < 4; ++i) {
            *(float4*)&sA[(qq + i) * KS + c0] =
                make_float4(Sr[i][0] * nrm[i][0], Si[i][0] * nrm[i][0],
                            Sr[i][1] * nrm[i][1], Si[i][1] * nrm[i][1]);
            *(float4*)&sA[(qq + i) * KS + c0 + 32] =
                make_float4(Sr[i][2] * nrm[i][2], Si[i][2] * nrm[i][2],
                            Sr[i][3] * nrm[i][3], Si[i][3] * nrm[i][3]);
        }
        __syncthreads();

        // ---- Y += A . V : packed FFMA2, natural layouts ----
        #pragma unroll 2
        for (int kk = 0; kk < TK; kk += 2) {
            ulonglong2 av[4];              // .x = A @ kk, .y = A @ kk+1
            #pragma unroll
            for (int i = 0; i < 4; ++i)
                av[i] = *(const ulonglong2*)(sA + (qq + i) * KS + kk);
            const ulonglong2 vA = *(const ulonglong2*)(sV + kk * KS + c0);
            const ulonglong2 vB = *(const ulonglong2*)(sV + kk * KS + c0 + 32);
            const ulonglong2 vC = *(const ulonglong2*)(sV + (kk + 1) * KS + c0);
            const ulonglong2 vD = *(const ulonglong2*)(sV + (kk + 1) * KS + c0 + 32);
            const u64 v0 = vA.x, v1 = vA.y, v2 = vB.x, v3 = vB.y;
            const u64 w0 = swp(v0), w1 = swp(v1), w2 = swp(v2), w3 = swp(v3);
            const u64 v4 = vC.x, v5 = vC.y, v6 = vD.x, v7 = vD.y;
            const u64 w4 = swp(v4), w5 = swp(v5), w6 = swp(v6), w7 = swp(v7);
            #pragma unroll
            for (int i = 0; i < 4; ++i) {
                const u64 aa = av[i].x;    // @ kk
                FFMA2(P[i][0], aa, v0);  FFMA2(Qc[i][0], aa, w0);
                FFMA2(P[i][1], aa, v1);  FFMA2(Qc[i][1], aa, w1);
                FFMA2(P[i][2], aa, v2);  FFMA2(Qc[i][2], aa, w2);
                FFMA2(P[i][3], aa, v3);  FFMA2(Qc[i][3], aa, w3);
                const u64 ab = av[i].y;    // @ kk+1
                FFMA2(P[i][0], ab, v4);  FFMA2(Qc[i][0], ab, w4);
                FFMA2(P[i][1], ab, v5);  FFMA2(Qc[i][1], ab, w5);
                FFMA2(P[i][2], ab, v6);  FFMA2(Qc[i][2], ab, w6);
                FFMA2(P[i][3], ab, v7);  FFMA2(Qc[i][3], ab, w7);
            }
        }
    }

    // ---- epilogue: combine lanes, divide by denominator, write [B,Q,V,2] ----
    // thread's v cols: c0, c0+1, c0+32, c0+33
    float2* o = (float2*)gout + (size_t)(b * QLEN + q0) * VH;
    #pragma unroll
    for (int i = 0; i < 4; ++i) {
        const float inv = 1.0f / Z[i];
        float yr0 = lo32(P[i][0]) - hi32(P[i][0]);
        float yi0 = lo32(Qc[i][0]) + hi32(Qc[i][0]);
        float yr1 = lo32(P[i][1]) - hi32(P[i][1]);
        float yi1 = lo32(Qc[i][1]) + hi32(Qc[i][1]);
        float yr2 = lo32(P[i][2]) - hi32(P[i][2]);
        float yi2 = lo32(Qc[i][2]) + hi32(Qc[i][2]);
        float yr3 = lo32(P[i][3]) - hi32(P[i][3]);
        float yi3 = lo32(Qc[i][3]) + hi32(Qc[i][3]);
        *(float4*)&o[(qq + i) * VH + c0] =
            make_float4(yr0 * inv, yi0 * inv, yr1 * inv, yi1 * inv);
        *(float4*)&o[(qq + i) * VH + c0 + 32] =
            make_float4(yr2 * inv, yi2 * inv, yr3 * inv, yi3 * inv);
    }
}

extern "C" void kernel_launch(void* const* d_in, const int* in_sizes, int n_in,
                              void* d_out, int out_size)
{
    const float* q = (const float*)d_in[0];
    const float* k = (const float*)d_in[1];
    const float* v = (const float*)d_in[2];
    float* out = (float*)d_out;

    const size_t smem = (size_t)(TQ * QS + DH * KS + TK * KS + TQ * KS) * sizeof(float2); // 135168 B
    cudaFuncSetAttribute(cdpa_kernel,
                         cudaFuncAttributeMaxDynamicSharedMemorySize, (int)smem);
    dim3 grid(QLEN / TQ, NB);
    cdpa_kernel<<<grid, 256, smem>>>(q, k, v, out);
}

// round 4
// speedup vs baseline: 1.9085x; 1.0027x over previous
#include <cuda_runtime.h>

// ComplexDotProductAttention on GB300 (sm_103a): B=4, Q=K=4096, D=V=64, complex fp32.
// Flash-style single pass over K. 512 threads/CTA, 4q x 2k complex per thread.
// ty = tid>>5 -> q-rows warp-uniform => Q/A shared-loads are warp broadcasts.
// Packed fma.rn.f32x2 with register-side swap of the shared operand:
//   S:  accS += (Qr,Qi)*(Kr,Ki) -> Sr = lo+hi ; accD += (Qr,Qi)*(Ki,Kr) -> Si = lo-hi
//   AV: P += (Ar,Ai)*(Vr,Vi) -> Yr = lo-hi    ; Qc += (Ar,Ai)*(Vi,Vr) -> Yi = lo+hi

#define NB      4
#define QLEN    4096
#define KLEN    4096
#define DH      64
#define VH      64
#define TQ      64
#define TK      64
#define QS      66   // sQ row stride in float2
#define KS      66   // sKT/sV/sA row stride in float2
#define NT      512

#define FFMA2(acc, a, b) \
    asm("fma.rn.f32x2 %0, %1, %2, %0;" : "+l"(acc) : "l"(a), "l"(b))

typedef unsigned long long u64;

__device__ __forceinline__ float lo32(u64 v) { return __uint_as_float((unsigned)v); }
__device__ __forceinline__ float hi32(u64 v) { return __uint_as_float((unsigned)(v >> 32)); }
__device__ __forceinline__ u64 pk2(float lo, float hi) {
    u64 r; asm("mov.b64 %0, {%1, %2};" : "=l"(r) : "f"(lo), "f"(hi)); return r;
}
__device__ __forceinline__ u64 swp(u64 v) { return pk2(hi32(v), lo32(v)); }
__device__ __forceinline__ u64 dup2(float x) {
    u64 r; asm("mov.b64 %0, {%1, %1};" : "=l"(r) : "f"(x)); return r;
}
__device__ __forceinline__ u64 mul2(u64 a, u64 b) {
    u64 r; asm("mul.rn.f32x2 %0, %1, %2;" : "=l"(r) : "l"(a), "l"(b)); return r;
}

__global__ __launch_bounds__(NT, 1)
void cdpa_kernel(const float* __restrict__ gq,
                 const float* __restrict__ gk,
                 const float* __restrict__ gv,
                 float* __restrict__ gout)
{
    extern __shared__ char smem_raw[];
    float2* sQ  = (float2*)smem_raw;       // [TQ][QS]  (Qr,Qi), scaled
    float2* sKT = sQ  + TQ * QS;           // [DH][KS]  (Kr,Ki), k across
    float2* sV  = sKT + DH * KS;           // [TK][KS]  (Vr,Vi), v across
    float2* sA  = sV  + TK * KS;           // [TQ][KS]  (Ar,Ai)

    const int b   = blockIdx.y;
    const int q0  = blockIdx.x * TQ;
    const int tid = threadIdx.x;
    const int tx  = tid & 31;              // k / v group (32 lanes x 2 cols)
    const int ty  = tid >> 5;              // warp id == q group (warp-uniform)
    const int qq  = ty * 4;                // local q base (4 rows)
    const int c0  = 2 * tx;                // k/v cols: c0, c0+1

    const float scale = 0.125f;            // 1/sqrt(64)

    // ---- load Q tile once (natural layout), fold in scale ----
    {
        const float4* g = (const float4*)gq + (size_t)(b * QLEN + q0) * (DH * 2 / 4);
        #pragma unroll
        for (int i = 0; i < 4; ++i) {
            int e = i * NT + tid;          // 0..2047 float4s
            int row = e >> 5, dp = e & 31; // dp indexes pairs of d
            float4 v = g[e];               // (Qr_d, Qi_d, Qr_d1, Qi_d1)
            sQ[row * QS + 2 * dp    ] = make_float2(v.x * scale, v.y * scale);
            sQ[row * QS + 2 * dp + 1] = make_float2(v.z * scale, v.w * scale);
        }
    }

    float m[4], Z[4], nrm[4][2];
    u64 P[4][2], Qc[4][2];
    #pragma unroll
    for (int i = 0; i < 4; ++i) {
        m[i] = -1e30f;
        Z[i] = 0.0f;
        #pragma unroll
        for (int j = 0; j < 2; ++j) { P[i][j] = 0ull; Qc[i][j] = 0ull; }
    }

    const size_t kvbase4 = (size_t)(b) * KLEN * (DH * 2 / 4);

    for (int kt = 0; kt < KLEN; kt += TK) {
        __syncthreads();  // prior-iter reads of sKT/sV/sA complete before overwrite

        // ---- load K tile transposed: sKT[d][k] = (Kr,Ki) ----
        {
            const float4* g = (const float4*)gk + kvbase4 + (size_t)kt * 32;
            #pragma unroll
            for (int i = 0; i < 4; ++i) {
                int e = i * NT + tid;
                int krow = e >> 5, dp = e & 31;
                float4 v = g[e];
                sKT[(2 * dp    ) * KS + krow] = make_float2(v.x, v.y);
                sKT[(2 * dp + 1) * KS + krow] = make_float2(v.z, v.w);
            }
        }
        // ---- load V tile straight: sV[k][v] = (Vr,Vi) ----
        {
            const float4* g = (const float4*)gv + kvbase4 + (size_t)kt * 32;
            #pragma unroll
            for (int i = 0; i < 4; ++i) {
                int e = i * NT + tid;
                int row = e >> 5, col = e & 31;
                *(float4*)&sV[row * KS + col * 2] = g[e];
            }
        }
        __syncthreads();

        // ---- S gemm: packed FFMA2 ----
        u64 accS[4][2], accD[4][2];
        #pragma unroll
        for (int i = 0; i < 4; ++i)
            #pragma unroll
            for (int j = 0; j < 2; ++j) { accS[i][j] = 0ull; accD[i][j] = 0ull; }

        #pragma unroll 2
        for (int d = 0; d < DH; d += 2) {
            ulonglong2 qv[4];              // .x = Q pair @ d, .y = @ d+1 (warp-broadcast)
            #pragma unroll
            for (int i = 0; i < 4; ++i)
                qv[i] = *(const ulonglong2*)(sQ + (qq + i) * QS + d);
            const ulonglong2 kA = *(const ulonglong2*)(sKT + d * KS + c0);       // k c0,c0+1 @ d
            const ulonglong2 kC = *(const ulonglong2*)(sKT + (d + 1) * KS + c0); // @ d+1
            const u64 k0 = kA.x, k1 = kA.y, k4 = kC.x, k5 = kC.y;
            const u64 s0 = swp(k0), s1 = swp(k1), s4 = swp(k4), s5 = swp(k5);
            #pragma unroll
            for (int i = 0; i < 4; ++i) {
                const u64 qa = qv[i].x;    // @ d
                FFMA2(accS[i][0], qa, k0);  FFMA2(accD[i][0], qa, s0);
                FFMA2(accS[i][1], qa, k1);  FFMA2(accD[i][1], qa, s1);
                const u64 qb = qv[i].y;    // @ d+1
                FFMA2(accS[i][0], qb, k4);  FFMA2(accD[i][0], qb, s4);
                FFMA2(accS[i][1], qb, k5);  FFMA2(accD[i][1], qb, s5);
            }
        }

        // ---- unpack, norms; fold rsqrt into S (unit direction) ----
        float Sr[4][2], Si[4][2];
        #pragma unroll
        for (int i = 0; i < 4; ++i) {
            #pragma unroll
            for (int j = 0; j < 2; ++j) {
                float sr = lo32(accS[i][j]) + hi32(accS[i][j]);
                float si = lo32(accD[i][j]) - hi32(accD[i][j]);
                float s2v = sr * sr + si * si;
                float r = rsqrtf(s2v);
                float n = s2v * r;
                if (s2v < 1e-35f) { r = 0.0f; n = 0.0f; }
                nrm[i][j] = n;
                Sr[i][j] = sr * r;
                Si[i][j] = si * r;
            }
        }

        // ---- online softmax update (per q row, across all 32 lanes) ----
        #pragma unroll
        for (int i = 0; i < 4; ++i) {
            float tmax = fmaxf(nrm[i][0], nrm[i][1]);
            #pragma unroll
            for (int o = 16; o >= 1; o >>= 1)
                tmax = fmaxf(tmax, __shfl_xor_sync(0xffffffffu, tmax, o));
            float mn = fmaxf(m[i], tmax);
            float alpha = __expf(m[i] - mn);
            m[i] = mn;
            Z[i] *= alpha;
            const u64 ap = dup2(alpha);
            #pragma unroll
            for (int j = 0; j < 2; ++j) {
                P[i][j]  = mul2(P[i][j],  ap);
                Qc[i][j] = mul2(Qc[i][j], ap);
            }
            float esum = 0.0f;
            #pragma unroll
            for (int j = 0; j < 2; ++j) {
                float e = __expf(nrm[i][j] - mn);
                nrm[i][j] = e;
                esum += e;
            }
            #pragma unroll
            for (int o = 16; o >= 1; o >>= 1)
                esum += __shfl_xor_sync(0xffffffffu, esum, o);
            Z[i] += esum;
        }

        // ---- write A: cols {c0, c0+1} per q-row ----
        #pragma unroll
        for (int i = 0; i < 4; ++i) {
            *(float4*)&sA[(qq + i) * KS + c0] =
                make_float4(Sr[i][0] * nrm[i][0], Si[i][0] * nrm[i][0],
                            Sr[i][1] * nrm[i][1], Si[i][1] * nrm[i][1]);
        }
        __syncthreads();

        // ---- Y += A . V : packed FFMA2 ----
        #pragma unroll 2
        for (int kk = 0; kk < TK; kk += 2) {
            ulonglong2 av[4];              // .x = A @ kk, .y = A @ kk+1 (warp-broadcast)
            #pragma unroll
            for (int i = 0; i < 4; ++i)
                av[i] = *(const ulonglong2*)(sA + (qq + i) * KS + kk);
            const ulonglong2 vA = *(const ulonglong2*)(sV + kk * KS + c0);       // v c0,c0+1 @ kk
            const ulonglong2 vC = *(const ulonglong2*)(sV + (kk + 1) * KS + c0); // @ kk+1
            const u64 v0 = vA.x, v1 = vA.y, v4 = vC.x, v5 = vC.y;
            const u64 w0 = swp(v0), w1 = swp(v1), w4 = swp(v4), w5 = swp(v5);
            #pragma unroll
            for (int i = 0; i < 4; ++i) {
                const u64 aa = av[i].x;    // @ kk
                FFMA2(P[i][0], aa, v0);  FFMA2(Qc[i][0], aa, w0);
                FFMA2(P[i][1], aa, v1);  FFMA2(Qc[i][1], aa, w1);
                const u64 ab = av[i].y;    // @ kk+1
                FFMA2(P[i][0], ab, v4);  FFMA2(Qc[i][0], ab, w4);
                FFMA2(P[i][1], ab, v5);  FFMA2(Qc[i][1], ab, w5);
            }
        }
    }

    // ---- epilogue: combine lanes, divide by denominator, write [B,Q,V,2] ----
    float2* o = (float2*)gout + (size_t)(b * QLEN + q0) * VH;
    #pragma unroll
    for (int i = 0; i < 4; ++i) {
        const float inv = 1.0f / Z[i];
        float yr0 = lo32(P[i][0]) - hi32(P[i][0]);
        float yi0 = lo32(Qc[i][0]) + hi32(Qc[i][0]);
        float yr1 = lo32(P[i][1]) - hi32(P[i][1]);
        float yi1 = lo32(Qc[i][1]) + hi32(Qc[i][1]);
        *(float4*)&o[(qq + i) * VH + c0] =
            make_float4(yr0 * inv, yi0 * inv, yr1 * inv, yi1 * inv);
    }
}

extern "C" void kernel_launch(void* const* d_in, const int* in_sizes, int n_in,
                              void* d_out, int out_size)
{
    const float* q = (const float*)d_in[0];
    const float* k = (const float*)d_in[1];
    const float* v = (const float*)d_in[2];
    float* out = (float*)d_out;

    const size_t smem = (size_t)(TQ * QS + DH * KS + TK * KS + TQ * KS) * sizeof(float2); // 135168 B
    cudaFuncSetAttribute(cdpa_kernel,
                         cudaFuncAttributeMaxDynamicSharedMemorySize, (int)smem);
    dim3 grid(QLEN / TQ, NB);
    cdpa_kernel<<<grid, NT, smem>>>(q, k, v, out);
}

// round 5
// speedup vs baseline: 1.9239x; 1.0081x over previous
#include <cuda_runtime.h>

// ComplexDotProductAttention on GB300 (sm_103a): B=4, Q=K=4096, D=V=64, complex fp32.
// Flash-style single pass over K. 256 threads/CTA, 4q x 4k complex per thread.
// Karatsuba 3-mult complex MAC with packed fma.rn.f32x2:
//   S:  accP += (Qr,Qi)*(Kr,Ki)            -> T1=lo, T2=hi
//       accT += (Qr-Qi,dup)*(sum_k0,sum_k1) where sum=Kr+Ki
//       Sr = T1+T2 ; Si = T3 - T1 + T2
//   AV: P += (Ar,Ai)*(Vr,Vi) ; PT += (Ar+Ai,dup)*(Vr+Vi pairs)
//       Yr = T1-T2 ; Yi = T3 - T1 - T2

#define NB      4
#define QLEN    4096
#define KLEN    4096
#define DH      64
#define VH      64
#define TQ      64
#define TK      64
#define FS      66   // float2 row stride (sQ,sQD,sKT,sV,sA)
#define SS      68   // float row stride (sKS,sVS sum tiles)
#define NT      256

#define FFMA2(acc, a, b) \
    asm("fma.rn.f32x2 %0, %1, %2, %0;" : "+l"(acc) : "l"(a), "l"(b))

typedef unsigned long long u64;

__device__ __forceinline__ float lo32(u64 v) { return __uint_as_float((unsigned)v); }
__device__ __forceinline__ float hi32(u64 v) { return __uint_as_float((unsigned)(v >> 32)); }
__device__ __forceinline__ u64 dup2(float x) {
    u64 r; asm("mov.b64 %0, {%1, %1};" : "=l"(r) : "f"(x)); return r;
}
__device__ __forceinline__ u64 mul2(u64 a, u64 b) {
    u64 r; asm("mul.rn.f32x2 %0, %1, %2;" : "=l"(r) : "l"(a), "l"(b)); return r;
}

__global__ __launch_bounds__(NT, 1)
void cdpa_kernel(const float* __restrict__ gq,
                 const float* __restrict__ gk,
                 const float* __restrict__ gv,
                 float* __restrict__ gout)
{
    extern __shared__ char smem_raw[];
    float2* sQ  = (float2*)smem_raw;       // [TQ][FS]  (Qr,Qi), scaled
    float2* sQD = sQ  + TQ * FS;           // [TQ][FS]  (Qr-Qi, Qr-Qi), scaled
    float2* sKT = sQD + TQ * FS;           // [DH][FS]  (Kr,Ki), k across
    float2* sV  = sKT + DH * FS;           // [TK][FS]  (Vr,Vi), v across
    float2* sA  = sV  + TK * FS;           // [TQ][FS]  (Ar,Ai)
    float*  sKS = (float*)(sA + TQ * FS);  // [DH][SS]  Kr+Ki, k across
    float*  sVS = sKS + DH * SS;           // [TK][SS]  Vr+Vi, v across

    const int b   = blockIdx.y;
    const int q0  = blockIdx.x * TQ;
    const int tid = threadIdx.x;
    const int tx  = tid & 15;              // k / v group
    const int ty  = tid >> 4;              // q group
    const int qq  = ty * 4;                // local q base (4 rows)
    const int c0  = 2 * tx;                // k/v cols: c0, c0+1, c0+32, c0+33

    const float scale = 0.125f;            // 1/sqrt(64)

    // ---- load Q tile once: pairs + dup'd diffs, fold in scale ----
    {
        const float4* g = (const float4*)gq + (size_t)(b * QLEN + q0) * (DH * 2 / 4);
        #pragma unroll
        for (int i = 0; i < 8; ++i) {
            int e = i * NT + tid;          // 0..2047 float4s
            int row = e >> 5, dp = e & 31; // dp indexes pairs of d
            float4 v = g[e];               // (Qr_d, Qi_d, Qr_d1, Qi_d1)
            float qr0 = v.x * scale, qi0 = v.y * scale;
            float qr1 = v.z * scale, qi1 = v.w * scale;
            sQ [row * FS + 2 * dp    ] = make_float2(qr0, qi0);
            sQ [row * FS + 2 * dp + 1] = make_float2(qr1, qi1);
            sQD[row * FS + 2 * dp    ] = make_float2(qr0 - qi0, qr0 - qi0);
            sQD[row * FS + 2 * dp + 1] = make_float2(qr1 - qi1, qr1 - qi1);
        }
    }

    float m[4], Z[4], nrm[4][4];
    u64 P[4][4], PT[4][2];
    #pragma unroll
    for (int i = 0; i < 4; ++i) {
        m[i] = -1e30f;
        Z[i] = 0.0f;
        #pragma unroll
        for (int j = 0; j < 4; ++j) P[i][j] = 0ull;
        PT[i][0] = 0ull; PT[i][1] = 0ull;
    }

    const size_t kvbase4 = (size_t)(b) * KLEN * (DH * 2 / 4);

    for (int kt = 0; kt < KLEN; kt += TK) {
        __syncthreads();  // prior-iter reads of sKT/sV/sA/sKS/sVS complete

        // ---- load K tile transposed + sums: sKT[d][k], sKS[d][k] ----
        {
            const float4* g = (const float4*)gk + kvbase4 + (size_t)kt * 32;
            #pragma unroll
            for (int i = 0; i < 8; ++i) {
                int e = i * NT + tid;
                int krow = e >> 5, dp = e & 31;
                float4 v = g[e];
                sKT[(2 * dp    ) * FS + krow] = make_float2(v.x, v.y);
                sKT[(2 * dp + 1) * FS + krow] = make_float2(v.z, v.w);
                sKS[(2 * dp    ) * SS + krow] = v.x + v.y;
                sKS[(2 * dp + 1) * SS + krow] = v.z + v.w;
            }
        }
        // ---- load V tile straight + sums: sV[k][v], sVS[k][v] ----
        {
            const float4* g = (const float4*)gv + kvbase4 + (size_t)kt * 32;
            #pragma unroll
            for (int i = 0; i < 8; ++i) {
                int e = i * NT + tid;
                int row = e >> 5, col = e & 31;
                float4 v = g[e];
                *(float4*)&sV[row * FS + col * 2] = v;
                sVS[row * SS + 2 * col    ] = v.x + v.y;
                sVS[row * SS + 2 * col + 1] = v.z + v.w;
            }
        }
        __syncthreads();

        // ---- S gemm: Karatsuba packed FFMA2 ----
        u64 accP[4][4], accT[4][2];
        #pragma unroll
        for (int i = 0; i < 4; ++i) {
            #pragma unroll
            for (int j = 0; j < 4; ++j) accP[i][j] = 0ull;
            accT[i][0] = 0ull; accT[i][1] = 0ull;
        }

        #pragma unroll 2
        for (int d = 0; d < DH; d += 2) {
            ulonglong2 qv[4], qd[4];       // .x @ d, .y @ d+1 (half-warp broadcast)
            #pragma unroll
            for (int i = 0; i < 4; ++i) {
                qv[i] = *(const ulonglong2*)(sQ  + (qq + i) * FS + d);
                qd[i] = *(const ulonglong2*)(sQD + (qq + i) * FS + d);
            }
            const ulonglong2 kA = *(const ulonglong2*)(sKT + d * FS + c0);            // k c0,c0+1 @ d
            const ulonglong2 kB = *(const ulonglong2*)(sKT + d * FS + c0 + 32);       // k +32 @ d
            const ulonglong2 kC = *(const ulonglong2*)(sKT + (d + 1) * FS + c0);      // @ d+1
            const ulonglong2 kD = *(const ulonglong2*)(sKT + (d + 1) * FS + c0 + 32);
            const u64 ks0 = *(const u64*)(sKS + d * SS + c0);
            const u64 ks1 = *(const u64*)(sKS + d * SS + c0 + 32);
            const u64 ks2 = *(const u64*)(sKS + (d + 1) * SS + c0);
            const u64 ks3 = *(const u64*)(sKS + (d + 1) * SS + c0 + 32);
            #pragma unroll
            for (int i = 0; i < 4; ++i) {
                const u64 qa = qv[i].x, da = qd[i].x;     // @ d
                FFMA2(accP[i][0], qa, kA.x);  FFMA2(accP[i][1], qa, kA.y);
                FFMA2(accP[i][2], qa, kB.x);  FFMA2(accP[i][3], qa, kB.y);
                FFMA2(accT[i][0], da, ks0);   FFMA2(accT[i][1], da, ks1);
                const u64 qb = qv[i].y, db = qd[i].y;     // @ d+1
                FFMA2(accP[i][0], qb, kC.x);  FFMA2(accP[i][1], qb, kC.y);
                FFMA2(accP[i][2], qb, kD.x);  FFMA2(accP[i][3], qb, kD.y);
                FFMA2(accT[i][0], db, ks2);   FFMA2(accT[i][1], db, ks3);
            }
        }

        // ---- combine, norms; fold rsqrt into S (unit direction) ----
        float Sr[4][4], Si[4][4];
        #pragma unroll
        for (int i = 0; i < 4; ++i) {
            float t3[4] = { lo32(accT[i][0]), hi32(accT[i][0]),
                            lo32(accT[i][1]), hi32(accT[i][1]) };
            #pragma unroll
            for (int j = 0; j < 4; ++j) {
                float t1 = lo32(accP[i][j]), t2 = hi32(accP[i][j]);
                float sr = t1 + t2;
                float si = t3[j] - t1 + t2;
                float s2v = sr * sr + si * si;
                float r = rsqrtf(s2v);
                float n = s2v * r;
                if (s2v < 1e-35f) { r = 0.0f; n = 0.0f; }
                nrm[i][j] = n;
                Sr[i][j] = sr * r;
                Si[i][j] = si * r;
            }
        }

        // ---- online softmax update (per q row, across 16 tx lanes) ----
        #pragma unroll
        for (int i = 0; i < 4; ++i) {
            float tmax = fmaxf(fmaxf(nrm[i][0], nrm[i][1]), fmaxf(nrm[i][2], nrm[i][3]));
            #pragma unroll
            for (int o = 8; o >= 1; o >>= 1)
                tmax = fmaxf(tmax, __shfl_xor_sync(0xffffffffu, tmax, o, 16));
            float mn = fmaxf(m[i], tmax);
            float alpha = __expf(m[i] - mn);
            m[i] = mn;
            Z[i] *= alpha;
            const u64 ap = dup2(alpha);
            #pragma unroll
            for (int j = 0; j < 4; ++j) P[i][j] = mul2(P[i][j], ap);
            PT[i][0] = mul2(PT[i][0], ap);
            PT[i][1] = mul2(PT[i][1], ap);
            float esum = 0.0f;
            #pragma unroll
            for (int j = 0; j < 4; ++j) {
                float e = __expf(nrm[i][j] - mn);
                nrm[i][j] = e;
                esum += e;
            }
            #pragma unroll
            for (int o = 8; o >= 1; o >>= 1)
                esum += __shfl_xor_sync(0xffffffffu, esum, o, 16);
            Z[i] += esum;
        }

        // ---- write A: cols {c0,c0+1} and {c0+32,c0+33} ----
        #pragma unroll
        for (int i = 0; i < 4; ++i) {
            *(float4*)&sA[(qq + i) * FS + c0] =
                make_float4(Sr[i][0] * nrm[i][0], Si[i][0] * nrm[i][0],
                            Sr[i][1] * nrm[i][1], Si[i][1] * nrm[i][1]);
            *(float4*)&sA[(qq + i) * FS + c0 + 32] =
                make_float4(Sr[i][2] * nrm[i][2], Si[i][2] * nrm[i][2],
                            Sr[i][3] * nrm[i][3], Si[i][3] * nrm[i][3]);
        }
        __syncthreads();

        // ---- Y += A . V : Karatsuba packed FFMA2 ----
        #pragma unroll 2
        for (int kk = 0; kk < TK; kk += 2) {
            ulonglong2 av[4];              // .x = (Ar,Ai)@kk, .y @ kk+1 (broadcast)
            #pragma unroll
            for (int i = 0; i < 4; ++i)
                av[i] = *(const ulonglong2*)(sA + (qq + i) * FS + kk);
            const ulonglong2 vA = *(const ulonglong2*)(sV + kk * FS + c0);
            const ulonglong2 vB = *(const ulonglong2*)(sV + kk * FS + c0 + 32);
            const ulonglong2 vC = *(const ulonglong2*)(sV + (kk + 1) * FS + c0);
            const ulonglong2 vD = *(const ulonglong2*)(sV + (kk + 1) * FS + c0 + 32);
            const u64 vs0 = *(const u64*)(sVS + kk * SS + c0);
            const u64 vs1 = *(const u64*)(sVS + kk * SS + c0 + 32);
            const u64 vs2 = *(const u64*)(sVS + (kk + 1) * SS + c0);
            const u64 vs3 = *(const u64*)(sVS + (kk + 1) * SS + c0 + 32);
            #pragma unroll
            for (int i = 0; i < 4; ++i) {
                const u64 a0 = av[i].x;                       // @ kk
                const u64 as0 = dup2(lo32(a0) + hi32(a0));
                FFMA2(P[i][0], a0, vA.x);  FFMA2(P[i][1], a0, vA.y);
                FFMA2(P[i][2], a0, vB.x);  FFMA2(P[i][3], a0, vB.y);
                FFMA2(PT[i][0], as0, vs0); FFMA2(PT[i][1], as0, vs1);
                const u64 a1 = av[i].y;                       // @ kk+1
                const u64 as1 = dup2(lo32(a1) + hi32(a1));
                FFMA2(P[i][0], a1, vC.x);  FFMA2(P[i][1], a1, vC.y);
                FFMA2(P[i][2], a1, vD.x);  FFMA2(P[i][3], a1, vD.y);
                FFMA2(PT[i][0], as1, vs2); FFMA2(PT[i][1], as1, vs3);
            }
        }
    }

    // ---- epilogue: combine, divide by denominator, write [B,Q,V,2] ----
    float2* o = (float2*)gout + (size_t)(b * QLEN + q0) * VH;
    #pragma unroll
    for (int i = 0; i < 4; ++i) {
        const float inv = 1.0f / Z[i];
        float t3[4] = { lo32(PT[i][0]), hi32(PT[i][0]),
                        lo32(PT[i][1]), hi32(PT[i][1]) };
        float yr[4], yi[4];
        #pragma unroll
        for (int j = 0; j < 4; ++j) {
            float t1 = lo32(P[i][j]), t2 = hi32(P[i][j]);
            yr[j] = (t1 - t2) * inv;
            yi[j] = (t3[j] - t1 - t2) * inv;
        }
        *(float4*)&o[(qq + i) * VH + c0] =
            make_float4(yr[0], yi[0], yr[1], yi[1]);
        *(float4*)&o[(qq + i) * VH + c0 + 32] =
            make_float4(yr[2], yi[2], yr[3], yi[3]);
    }
}

extern "C" void kernel_launch(void* const* d_in, const int* in_sizes, int n_in,
                              void* d_out, int out_size)
{
    const float* q = (const float*)d_in[0];
    const float* k = (const float*)d_in[1];
    const float* v = (const float*)d_in[2];
    float* out = (float*)d_out;

    const size_t smem = (size_t)(5 * TQ * FS) * sizeof(float2)
                      + (size_t)(2 * DH * SS) * sizeof(float);   // 168960 + 34816 = 203776 B
    cudaFuncSetAttribute(cdpa_kernel,
                         cudaFuncAttributeMaxDynamicSharedMemorySize, (int)smem);
    dim3 grid(QLEN / TQ, NB);
    cdpa_kernel<<<grid, NT, smem>>>(q, k, v, out);
}

// round 7
// speedup vs baseline: 4.6709x; 2.4278x over previous
#include <cuda_runtime.h>
#include <cuda_bf16.h>

typedef unsigned int u32;
typedef unsigned long long u64;

#define NB    4
#define QLEN  4096
#define KLEN  4096
#define VH    64
#define TQ    128
#define TK    64
#define NT    256
#define PITCH 272            // bytes per tile row: 128 bf16 + 8 pad

// ---- smem byte offsets ----
#define SM_QH   0
#define SM_QL   34816
#define SM_KRH  69632        // K tiles; A tiles reuse this region
#define SM_AH   69632
#define SM_KRL  (69632 + 17408)
#define SM_KIH  (69632 + 34816)
#define SM_AL   (69632 + 34816)
#define SM_KIL  (69632 + 52224)
#define SM_VRH  139264
#define SM_VRL  (139264 + 17408)
#define SM_VIH  (139264 + 34816)
#define SM_VIL  (139264 + 52224)
#define SM_ZRED 208896       // float[2][128]
#define SM_TOTAL 209920

#define LDSM4(R, addr) \
    asm volatile("ldmatrix.sync.aligned.m8n8.x4.shared.b16 {%0,%1,%2,%3}, [%4];" \
        : "=r"((R)[0]), "=r"((R)[1]), "=r"((R)[2]), "=r"((R)[3]) : "r"(addr))

#define MMA(D, A, B0, B1) \
    asm volatile("mma.sync.aligned.m16n8k16.row.col.f32.bf16.bf16.f32 " \
        "{%0,%1,%2,%3}, {%4,%5,%6,%7}, {%8,%9}, {%0,%1,%2,%3};" \
        : "+f"((D)[0]), "+f"((D)[1]), "+f"((D)[2]), "+f"((D)[3]) \
        : "r"((A)[0]), "r"((A)[1]), "r"((A)[2]), "r"((A)[3]), "r"(B0), "r"(B1))

__device__ __forceinline__ u32 smem_u32(const void* p) {
    u32 a;
    asm("{ .reg .u64 t; cvta.to.shared.u64 t, %1; cvt.u32.u64 %0, t; }"
        : "=r"(a) : "l"(p));
    return a;
}
__device__ __forceinline__ void split2(float a, float b, u32& hp, u32& lp) {
    __nv_bfloat16 ha = __float2bfloat16(a), hb = __float2bfloat16(b);
    float la = a - __bfloat162float(ha), lb = b - __bfloat162float(hb);
    __nv_bfloat16 lA = __float2bfloat16(la), lB = __float2bfloat16(lb);
    hp = (u32)__bfloat16_as_ushort(ha) | ((u32)__bfloat16_as_ushort(hb) << 16);
    lp = (u32)__bfloat16_as_ushort(lA) | ((u32)__bfloat16_as_ushort(lB) << 16);
}
__device__ __forceinline__ void split4(float a, float b, float c, float d,
                                       u64& hp, u64& lp) {
    u32 h0, l0, h1, l1;
    split2(a, b, h0, l0);
    split2(c, d, h1, l1);
    hp = (u64)h0 | ((u64)h1 << 32);
    lp = (u64)l0 | ((u64)l1 << 32);
}

__global__ __launch_bounds__(NT, 1)
void cdpa_mma_kernel(const float* __restrict__ gq,
                     const float* __restrict__ gk,
                     const float* __restrict__ gv,
                     float* __restrict__ gout)
{
    extern __shared__ char sm[];
    const u32 smb = smem_u32(sm);
    const int tid = threadIdx.x;
    const int lane = tid & 31, wid = tid >> 5;
    const int wq = wid >> 1, wk = wid & 1;
    const int b = blockIdx.y, q0 = blockIdx.x * TQ;

    // ---- ldmatrix lane address components ----
    // A-operand (16x16): lanes 0-15 -> rows 0-15 k-lo, 16-31 -> rows k-hi
    const int arow = lane & 15, akb = lane >> 4;
    // B-operand (8n x 16k as x4 = 16n): n = (L&7)+8*(L>>4), kblk = (L>>3)&1
    const int bn = (lane & 7) + ((lane >> 4) << 3), bkb = (lane >> 3) & 1;

    u32 aqH[2], aqL[2], aaH[2], aaL[2], bS[2], bV[2];
    #pragma unroll
    for (int mf = 0; mf < 2; ++mf) {
        u32 ro = (u32)(32 * wq + 16 * mf + arow) * PITCH + akb * 16;
        aqH[mf] = smb + SM_QH + ro;
        aqL[mf] = smb + SM_QL + ro;
        aaH[mf] = smb + SM_AH + ro;
        aaL[mf] = smb + SM_AL + ro;
    }
    #pragma unroll
    for (int h = 0; h < 2; ++h) {
        u32 ro = (u32)(32 * wk + 16 * h + bn) * PITCH + bkb * 16;
        bS[h] = smb + SM_KRH + ro;
        bV[h] = smb + SM_VRH + ro;
    }

    // ---- load Q tile once: scale 1/8, bf16 hi/lo split ----
    {
        const float4* g = (const float4*)gq + (size_t)(b * QLEN + q0) * 32;
        #pragma unroll 4
        for (int it = 0; it < 16; ++it) {
            int e = it * NT + tid;
            int row = e >> 5, c4 = e & 31;
            float4 v = g[e];
            v.x *= 0.125f; v.y *= 0.125f; v.z *= 0.125f; v.w *= 0.125f;
            u64 hp, lp;
            split4(v.x, v.y, v.z, v.w, hp, lp);
            u32 off = (u32)row * PITCH + c4 * 8;
            *(u64*)(sm + SM_QH + off) = hp;
            *(u64*)(sm + SM_QL + off) = lp;
        }
    }

    float yr[2][4][4], yi[2][4][4], Zp[2][2];
    #pragma unroll
    for (int mf = 0; mf < 2; ++mf) {
        Zp[mf][0] = 0.0f; Zp[mf][1] = 0.0f;
        #pragma unroll
        for (int nf = 0; nf < 4; ++nf)
            #pragma unroll
            for (int r = 0; r < 4; ++r) { yr[mf][nf][r] = 0.0f; yi[mf][nf][r] = 0.0f; }
    }

    for (int kt = 0; kt < KLEN; kt += TK) {
        __syncthreads();   // prior-iter ldmatrix reads of K/A/V done

        // ---- K tile: KR=(Kr,Ki), KI=(Ki,-Kr), hi/lo split ----
        {
            const float4* g = (const float4*)gk + (size_t)(b * KLEN + kt) * 32;
            #pragma unroll 4
            for (int it = 0; it < 8; ++it) {
                int e = it * NT + tid;
                int row = e >> 5, c4 = e & 31;
                float4 v = g[e];
                u32 off = (u32)row * PITCH + c4 * 8;
                u64 hp, lp;
                split4(v.x, v.y, v.z, v.w, hp, lp);
                *(u64*)(sm + SM_KRH + off) = hp;
                *(u64*)(sm + SM_KRL + off) = lp;
                split4(v.y, -v.x, v.w, -v.z, hp, lp);
                *(u64*)(sm + SM_KIH + off) = hp;
                *(u64*)(sm + SM_KIL + off) = lp;
            }
        }
        // ---- V tile transposed: VR[v][2kk]=(Vr,-Vi), VI=(Vi,Vr) ----
        {
            int vcol = tid & 63;
            int kh = (tid >> 6) << 4;
            const float2* g = (const float2*)gv
                + ((size_t)(b * KLEN + kt + kh) * VH + vcol);
            #pragma unroll 4
            for (int j = 0; j < 16; ++j) {
                float2 t = g[(size_t)j * VH];
                u32 off = (u32)vcol * PITCH + (kh + j) * 4;
                u32 hp, lp;
                split2(t.x, -t.y, hp, lp);
                *(u32*)(sm + SM_VRH + off) = hp;
                *(u32*)(sm + SM_VRL + off) = lp;
                split2(t.y, t.x, hp, lp);
                *(u32*)(sm + SM_VIH + off) = hp;
                *(u32*)(sm + SM_VIL + off) = lp;
            }
        }
        __syncthreads();

        // ---- S gemm: Sr/Si[32q x 32kk] in registers, 3-term bf16 split ----
        float sr[2][4][4], si[2][4][4];
        #pragma unroll
        for (int mf = 0; mf < 2; ++mf)
            #pragma unroll
            for (int nf = 0; nf < 4; ++nf)
                #pragma unroll
                for (int r = 0; r < 4; ++r) { sr[mf][nf][r] = 0.0f; si[mf][nf][r] = 0.0f; }

        #pragma unroll
        for (int ks = 0; ks < 8; ++ks) {
            const u32 ko = ks * 32;
            u32 ah0[4], ah1[4], al0[4], al1[4];
            LDSM4(ah0, aqH[0] + ko); LDSM4(ah1, aqH[1] + ko);
            LDSM4(al0, aqL[0] + ko); LDSM4(al1, aqL[1] + ko);
            #pragma unroll
            for (int h = 0; h < 2; ++h) {
                u32 rh[4], rl[4], ih[4], il[4];
                LDSM4(rh, bS[h] + ko);
                LDSM4(rl, bS[h] + 17408 + ko);
                LDSM4(ih, bS[h] + 34816 + ko);
                LDSM4(il, bS[h] + 52224 + ko);
                MMA(sr[0][2*h],   ah0, rh[0], rh[1]); MMA(sr[0][2*h],   ah0, rl[0], rl[1]); MMA(sr[0][2*h],   al0, rh[0], rh[1]);
                MMA(sr[0][2*h+1], ah0, rh[2], rh[3]); MMA(sr[0][2*h+1], ah0, rl[2], rl[3]); MMA(sr[0][2*h+1], al0, rh[2], rh[3]);
                MMA(sr[1][2*h],   ah1, rh[0], rh[1]); MMA(sr[1][2*h],   ah1, rl[0], rl[1]); MMA(sr[1][2*h],   al1, rh[0], rh[1]);
                MMA(sr[1][2*h+1], ah1, rh[2], rh[3]); MMA(sr[1][2*h+1], ah1, rl[2], rl[3]); MMA(sr[1][2*h+1], al1, rh[2], rh[3]);
                MMA(si[0][2*h],   ah0, ih[0], ih[1]); MMA(si[0][2*h],   ah0, il[0], il[1]); MMA(si[0][2*h],   al0, ih[0], ih[1]);
                MMA(si[0][2*h+1], ah0, ih[2], ih[3]); MMA(si[0][2*h+1], ah0, il[2], il[3]); MMA(si[0][2*h+1], al0, ih[2], ih[3]);
                MMA(si[1][2*h],   ah1, ih[0], ih[1]); MMA(si[1][2*h],   ah1, il[0], il[1]); MMA(si[1][2*h],   al1, ih[0], ih[1]);
                MMA(si[1][2*h+1], ah1, ih[2], ih[3]); MMA(si[1][2*h+1], ah1, il[2], il[3]); MMA(si[1][2*h+1], al1, ih[2], ih[3]);
            }
        }

        __syncthreads();   // all warps done reading K region before A overwrites it

        // ---- epilogue: n=|S|, e=exp(n), A=S*e/n -> smem bf16 hi/lo ----
        #pragma unroll
        for (int mf = 0; mf < 2; ++mf) {
            const u32 rbase = (u32)(32 * wq + 16 * mf + (lane >> 2)) * PITCH;
            #pragma unroll
            for (int nf = 0; nf < 4; ++nf) {
                #pragma unroll
                for (int rr = 0; rr < 2; ++rr) {
                    #pragma unroll
                    for (int cc = 0; cc < 2; ++cc) {
                        float a = sr[mf][nf][rr * 2 + cc];
                        float bb = si[mf][nf][rr * 2 + cc];
                        float s2 = a * a + bb * bb;
                        float r = rsqrtf(s2);
                        float n = s2 * r;
                        float e = __expf(n);
                        float w = e * r;
                        if (s2 < 1e-30f) { w = 0.0f; e = 1.0f; }
                        Zp[mf][rr] += e;
                        u32 hp, lp;
                        split2(a * w, bb * w, hp, lp);
                        u32 off = rbase + (u32)rr * (8 * PITCH)
                                + (u32)(32 * wk + 8 * nf + 2 * (lane & 3) + cc) * 4;
                        *(u32*)(sm + SM_AH + off) = hp;
                        *(u32*)(sm + SM_AL + off) = lp;
                    }
                }
            }
        }
        __syncthreads();

        // ---- AV gemm: Y += A.V' (accumulate in registers across tiles) ----
        #pragma unroll
        for (int ks = 0; ks < 8; ++ks) {
            const u32 ko = ks * 32;
            u32 ah0[4], ah1[4], al0[4], al1[4];
            LDSM4(ah0, aaH[0] + ko); LDSM4(ah1, aaH[1] + ko);
            LDSM4(al0, aaL[0] + ko); LDSM4(al1, aaL[1] + ko);
            #pragma unroll
            for (int h = 0; h < 2; ++h) {
                u32 rh[4], rl[4], ih[4], il[4];
                LDSM4(rh, bV[h] + ko);
                LDSM4(rl, bV[h] + 17408 + ko);
                LDSM4(ih, bV[h] + 34816 + ko);
                LDSM4(il, bV[h] + 52224 + ko);
                MMA(yr[0][2*h],   ah0, rh[0], rh[1]); MMA(yr[0][2*h],   ah0, rl[0], rl[1]); MMA(yr[0][2*h],   al0, rh[0], rh[1]);
                MMA(yr[0][2*h+1], ah0, rh[2], rh[3]); MMA(yr[0][2*h+1], ah0, rl[2], rl[3]); MMA(yr[0][2*h+1], al0, rh[2], rh[3]);
                MMA(yr[1][2*h],   ah1, rh[0], rh[1]); MMA(yr[1][2*h],   ah1, rl[0], rl[1]); MMA(yr[1][2*h],   al1, rh[0], rh[1]);
                MMA(yr[1][2*h+1], ah1, rh[2], rh[3]); MMA(yr[1][2*h+1], ah1, rl[2], rl[3]); MMA(yr[1][2*h+1], al1, rh[2], rh[3]);
                MMA(yi[0][2*h],   ah0, ih[0], ih[1]); MMA(yi[0][2*h],   ah0, il[0], il[1]); MMA(yi[0][2*h],   al0, ih[0], ih[1]);
                MMA(yi[0][2*h+1], ah0, ih[2], ih[3]); MMA(yi[0][2*h+1], ah0, il[2], il[3]); MMA(yi[0][2*h+1], al0, ih[2], ih[3]);
                MMA(yi[1][2*h],   ah1, ih[0], ih[1]); MMA(yi[1][2*h],   ah1, il[0], il[1]); MMA(yi[1][2*h],   al1, ih[0], ih[1]);
                MMA(yi[1][2*h+1], ah1, ih[2], ih[3]); MMA(yi[1][2*h+1], ah1, il[2], il[3]); MMA(yi[1][2*h+1], al1, ih[2], ih[3]);
            }
        }
    }

    // ---- Z reduction: quad shuffle + cross-k-warp via smem ----
    #pragma unroll
    for (int mf = 0; mf < 2; ++mf)
        #pragma unroll
        for (int rr = 0; rr < 2; ++rr) {
            float z = Zp[mf][rr];
            z += __shfl_xor_sync(0xffffffffu, z, 1);
            z += __shfl_xor_sync(0xffffffffu, z, 2);
            if ((lane & 3) == 0) {
                int q = 32 * wq + 16 * mf + 8 * rr + (lane >> 2);
                *(float*)(sm + SM_ZRED + (wk * 128 + q) * 4) = z;
            }
        }
    __syncthreads();

    // ---- output: Y / Z -> [B, Q, V, 2] ----
    #pragma unroll
    for (int mf = 0; mf < 2; ++mf) {
        #pragma unroll
        for (int rr = 0; rr < 2; ++rr) {
            int q = 32 * wq + 16 * mf + 8 * rr + (lane >> 2);
            float zq = *(float*)(sm + SM_ZRED + q * 4)
                     + *(float*)(sm + SM_ZRED + (128 + q) * 4);
            float inv = 1.0f / zq;
            float2* o = (float2*)gout + (size_t)(b * QLEN + q0 + q) * VH;
            #pragma unroll
            for (int nf = 0; nf < 4; ++nf) {
                #pragma unroll
                for (int cc = 0; cc < 2; ++cc) {
                    int v = 32 * wk + 8 * nf + 2 * (lane & 3) + cc;
                    o[v] = make_float2(yr[mf][nf][rr * 2 + cc] * inv,
                                       yi[mf][nf][rr * 2 + cc] * inv);
                }
            }
        }
    }
}

extern "C" void kernel_launch(void* const* d_in, const int* in_sizes, int n_in,
                              void* d_out, int out_size)
{
    const float* q = (const float*)d_in[0];
    const float* k = (const float*)d_in[1];
    const float* v = (const float*)d_in[2];
    float* out = (float*)d_out;

    cudaFuncSetAttribute(cdpa_mma_kernel,
                         cudaFuncAttributeMaxDynamicSharedMemorySize, SM_TOTAL);
    dim3 grid(QLEN / TQ, NB);
    cdpa_mma_kernel<<<grid, NT, SM_TOTAL>>>(q, k, v, out);
}

// round 8
// speedup vs baseline: 5.4582x; 1.1686x over previous
#include <cuda_runtime.h>
#include <cuda_bf16.h>

typedef unsigned int u32;
typedef unsigned long long u64;

#define NB     4
#define QLEN   4096
#define KLEN   4096
#define VH     64
#define TQ     128
#define TK     32
#define NT     256
#define NTILES 128          // KLEN / TK

#define PK 272              // K/Q tile row pitch (128 bf16 + 16B pad)
#define PV 144              // V/A tile row pitch (64 bf16 + 16B pad)

// ---- smem byte offsets ----
#define SM_QH   0           // 128 x 272
#define SM_QL   34816
#define SM_KRH  69632       // 32 x 272 each
#define SM_KRL  78336
#define SM_KIH  87040
#define SM_KIL  95744
#define SM_VRH  104448      // 64 x 144 each
#define SM_VRL  113664
#define SM_VIH  122880
#define SM_VIL  132096
#define SM_AH   141312      // 128 x 144 each
#define SM_AL   159744
#define SM_ZRED 178176      // float[2][128]
#define SM_TOTAL 179200

#define KPRE_TILE 34816     // 4 sub-tiles x 32 x 272
#define VPRE_TILE 36864     // 4 sub-tiles x 64 x 144

__device__ static __align__(16) unsigned char g_kpre[(size_t)NB * NTILES * KPRE_TILE];
__device__ static __align__(16) unsigned char g_vpre[(size_t)NB * NTILES * VPRE_TILE];

#define LDSM4(R, addr) \
    asm volatile("ldmatrix.sync.aligned.m8n8.x4.shared.b16 {%0,%1,%2,%3}, [%4];" \
        : "=r"((R)[0]), "=r"((R)[1]), "=r"((R)[2]), "=r"((R)[3]) : "r"(addr))

#define MMA(D, A, B0, B1) \
    asm volatile("mma.sync.aligned.m16n8k16.row.col.f32.bf16.bf16.f32 " \
        "{%0,%1,%2,%3}, {%4,%5,%6,%7}, {%8,%9}, {%0,%1,%2,%3};" \
        : "+f"((D)[0]), "+f"((D)[1]), "+f"((D)[2]), "+f"((D)[3]) \
        : "r"((A)[0]), "r"((A)[1]), "r"((A)[2]), "r"((A)[3]), "r"(B0), "r"(B1))

#define CP16(dst, src) \
    asm volatile("cp.async.cg.shared.global [%0], [%1], 16;" \
        :: "r"(dst), "l"(src) : "memory")
#define CP_COMMIT() asm volatile("cp.async.commit_group;" ::: "memory")
#define CP_WAIT1()  asm volatile("cp.async.wait_group 1;"  ::: "memory")

__device__ __forceinline__ u32 smem_u32(const void* p) {
    u32 a;
    asm("{ .reg .u64 t; cvta.to.shared.u64 t, %1; cvt.u32.u64 %0, t; }"
        : "=r"(a) : "l"(p));
    return a;
}
__device__ __forceinline__ void split2(float a, float b, u32& hp, u32& lp) {
    __nv_bfloat16 ha = __float2bfloat16(a), hb = __float2bfloat16(b);
    float la = a - __bfloat162float(ha), lb = b - __bfloat162float(hb);
    __nv_bfloat16 lA = __float2bfloat16(la), lB = __float2bfloat16(lb);
    hp = (u32)__bfloat16_as_ushort(ha) | ((u32)__bfloat16_as_ushort(hb) << 16);
    lp = (u32)__bfloat16_as_ushort(lA) | ((u32)__bfloat16_as_ushort(lB) << 16);
}
__device__ __forceinline__ void split4(float a, float b, float c, float d,
                                       u64& hp, u64& lp) {
    u32 h0, l0, h1, l1;
    split2(a, b, h0, l0);
    split2(c, d, h1, l1);
    hp = (u64)h0 | ((u64)h1 << 32);
    lp = (u64)l0 | ((u64)l1 << 32);
}

// ---- prep: K -> {KR=(Kr,Ki), KI=(Ki,-Kr)} hi/lo tiles ----
__global__ void prep_k_kernel(const float* __restrict__ gk) {
    int g = blockIdx.x * 8 + (threadIdx.x >> 5);    // global k-row (b*4096+krow)
    int lane = threadIdx.x & 31;
    int b = g >> 12, krow = g & 4095;
    int tile = krow >> 5, r = krow & 31;
    float4 v = ((const float4*)gk)[(size_t)g * 32 + lane];
    unsigned char* base = g_kpre + (size_t)(b * NTILES + tile) * KPRE_TILE
                        + r * PK + lane * 8;
    u64 hp, lp;
    split4(v.x, v.y, v.z, v.w, hp, lp);
    *(u64*)(base        ) = hp;
    *(u64*)(base +  8704) = lp;
    split4(v.y, -v.x, v.w, -v.z, hp, lp);
    *(u64*)(base + 17408) = hp;
    *(u64*)(base + 26112) = lp;
}

// ---- prep: V -> transposed {VR=(Vr,-Vi), VI=(Vi,Vr)} hi/lo tiles ----
__global__ void prep_v_kernel(const float* __restrict__ gv) {
    int bt = blockIdx.x;                            // b*128 + tile
    int b = bt >> 7, tile = bt & 127;
    int t = threadIdx.x;
    int k = t >> 3, vg = (t & 7) * 8;
    const float2* src = (const float2*)gv
        + ((size_t)(b * KLEN + tile * TK + k) * VH + vg);
    unsigned char* base = g_vpre + (size_t)bt * VPRE_TILE + k * 4;
    #pragma unroll
    for (int j = 0; j < 8; ++j) {
        float2 x = src[j];
        int ro = (vg + j) * PV;
        u32 hp, lp;
        split2(x.x, -x.y, hp, lp);
        *(u32*)(base + ro        ) = hp;
        *(u32*)(base + ro +  9216) = lp;
        split2(x.y, x.x, hp, lp);
        *(u32*)(base + ro + 18432) = hp;
        *(u32*)(base + ro + 27648) = lp;
    }
}

__device__ __forceinline__ void issue_k(u32 smb, int b, int t) {
    const unsigned char* src = g_kpre + (size_t)(b * NTILES + t) * KPRE_TILE;
    u32 dst = smb + SM_KRH;
    #pragma unroll 2
    for (int i = threadIdx.x; i < KPRE_TILE / 16; i += NT)
        CP16(dst + i * 16, src + (size_t)i * 16);
}
__device__ __forceinline__ void issue_v(u32 smb, int b, int t) {
    const unsigned char* src = g_vpre + (size_t)(b * NTILES + t) * VPRE_TILE;
    u32 dst = smb + SM_VRH;
    #pragma unroll 2
    for (int i = threadIdx.x; i < VPRE_TILE / 16; i += NT)
        CP16(dst + i * 16, src + (size_t)i * 16);
}

__global__ __launch_bounds__(NT, 1)
void cdpa_mma_kernel(const float* __restrict__ gq,
                     float* __restrict__ gout)
{
    extern __shared__ char sm[];
    const u32 smb = smem_u32(sm);
    const int tid = threadIdx.x;
    const int lane = tid & 31, wid = tid >> 5;
    const int wq = wid >> 1, wk = wid & 1;          // 4 q-warps x 2 k/v-warps
    const int b = blockIdx.y, q0 = blockIdx.x * TQ;

    // prefetch tile 0 before doing Q conversion work
    issue_k(smb, b, 0); CP_COMMIT();
    issue_v(smb, b, 0); CP_COMMIT();

    // ldmatrix lane addressing
    const int arow = lane & 15, akb = lane >> 4;
    const int bn = (lane & 7) + ((lane >> 4) << 3), bkb = (lane >> 3) & 1;

    u32 aqH[2], aqL[2], aaH[2], aaL[2];
    #pragma unroll
    for (int mf = 0; mf < 2; ++mf) {
        u32 rq = (u32)(32 * wq + 16 * mf + arow);
        aqH[mf] = smb + SM_QH + rq * PK + akb * 16;
        aqL[mf] = smb + SM_QL + rq * PK + akb * 16;
        aaH[mf] = smb + SM_AH + rq * PV + akb * 16;
        aaL[mf] = smb + SM_AL + rq * PV + akb * 16;
    }
    const u32 bKR = smb + SM_KRH + (u32)(16 * wk + bn) * PK + bkb * 16;
    u32 bV[2];
    #pragma unroll
    for (int h = 0; h < 2; ++h)
        bV[h] = smb + SM_VRH + (u32)(32 * wk + 16 * h + bn) * PV + bkb * 16;

    // ---- Q tile: scale 1/8, bf16 hi/lo split ----
    {
        const float4* g = (const float4*)gq + (size_t)(b * QLEN + q0) * 32;
        #pragma unroll 4
        for (int it = 0; it < 16; ++it) {
            int e = it * NT + tid;
            int row = e >> 5, c4 = e & 31;
            float4 v = g[e];
            v.x *= 0.125f; v.y *= 0.125f; v.z *= 0.125f; v.w *= 0.125f;
            u64 hp, lp;
            split4(v.x, v.y, v.z, v.w, hp, lp);
            u32 off = (u32)row * PK + c4 * 8;
            *(u64*)(sm + SM_QH + off) = hp;
            *(u64*)(sm + SM_QL + off) = lp;
        }
    }

    float yr[2][4][4], yi[2][4][4], Zp[2][2];
    #pragma unroll
    for (int mf = 0; mf < 2; ++mf) {
        Zp[mf][0] = 0.0f; Zp[mf][1] = 0.0f;
        #pragma unroll
        for (int nf = 0; nf < 4; ++nf)
            #pragma unroll
            for (int r = 0; r < 4; ++r) { yr[mf][nf][r] = 0.0f; yi[mf][nf][r] = 0.0f; }
    }

    for (int t = 0; t < NTILES; ++t) {
        CP_WAIT1();             // K[t] landed (V[t] may still fly)
        __syncthreads();

        // ---- S gemm: 32q x 16kk per warp, 3-term bf16 split ----
        float sr[2][2][4], si[2][2][4];
        #pragma unroll
        for (int mf = 0; mf < 2; ++mf)
            #pragma unroll
            for (int nf = 0; nf < 2; ++nf)
                #pragma unroll
                for (int r = 0; r < 4; ++r) { sr[mf][nf][r] = 0.0f; si[mf][nf][r] = 0.0f; }

        #pragma unroll
        for (int ks = 0; ks < 8; ++ks) {
            const u32 ko = ks * 32;
            u32 qh0[4], qh1[4], ql0[4], ql1[4];
            LDSM4(qh0, aqH[0] + ko); LDSM4(qh1, aqH[1] + ko);
            LDSM4(ql0, aqL[0] + ko); LDSM4(ql1, aqL[1] + ko);
            u32 rh[4], rl[4], ih[4], il[4];
            LDSM4(rh, bKR + ko);         LDSM4(rl, bKR +  8704 + ko);
            LDSM4(ih, bKR + 17408 + ko); LDSM4(il, bKR + 26112 + ko);
            MMA(sr[0][0], qh0, rh[0], rh[1]); MMA(sr[0][0], qh0, rl[0], rl[1]); MMA(sr[0][0], ql0, rh[0], rh[1]);
            MMA(sr[0][1], qh0, rh[2], rh[3]); MMA(sr[0][1], qh0, rl[2], rl[3]); MMA(sr[0][1], ql0, rh[2], rh[3]);
            MMA(sr[1][0], qh1, rh[0], rh[1]); MMA(sr[1][0], qh1, rl[0], rl[1]); MMA(sr[1][0], ql1, rh[0], rh[1]);
            MMA(sr[1][1], qh1, rh[2], rh[3]); MMA(sr[1][1], qh1, rl[2], rl[3]); MMA(sr[1][1], ql1, rh[2], rh[3]);
            MMA(si[0][0], qh0, ih[0], ih[1]); MMA(si[0][0], qh0, il[0], il[1]); MMA(si[0][0], ql0, ih[0], ih[1]);
            MMA(si[0][1], qh0, ih[2], ih[3]); MMA(si[0][1], qh0, il[2], il[3]); MMA(si[0][1], ql0, ih[2], ih[3]);
            MMA(si[1][0], qh1, ih[0], ih[1]); MMA(si[1][0], qh1, il[0], il[1]); MMA(si[1][0], ql1, ih[0], ih[1]);
            MMA(si[1][1], qh1, ih[2], ih[3]); MMA(si[1][1], qh1, il[2], il[3]); MMA(si[1][1], ql1, ih[2], ih[3]);
        }

        __syncthreads();        // every warp finished reading K[t]
        if (t + 1 < NTILES) issue_k(smb, b, t + 1);
        CP_COMMIT();

        // ---- epilogue: n=|S|, e=exp(n), A=S*e/n -> smem bf16 hi/lo ----
        #pragma unroll
        for (int mf = 0; mf < 2; ++mf) {
            const u32 rbase = (u32)(32 * wq + 16 * mf + (lane >> 2)) * PV;
            #pragma unroll
            for (int nf = 0; nf < 2; ++nf) {
                #pragma unroll
                for (int rr = 0; rr < 2; ++rr) {
                    #pragma unroll
                    for (int cc = 0; cc < 2; ++cc) {
                        float a = sr[mf][nf][rr * 2 + cc];
                        float bb = si[mf][nf][rr * 2 + cc];
                        float s2 = a * a + bb * bb;
                        float r = rsqrtf(s2);
                        float n = s2 * r;
                        float e = __expf(n);
                        float w = e * r;
                        if (s2 < 1e-30f) { w = 0.0f; e = 1.0f; }
                        Zp[mf][rr] += e;
                        u32 hp, lp;
                        split2(a * w, bb * w, hp, lp);
                        u32 off = rbase + (u32)rr * (8 * PV)
                                + (u32)(16 * wk + 8 * nf + 2 * (lane & 3) + cc) * 4;
                        *(u32*)(sm + SM_AH + off) = hp;
                        *(u32*)(sm + SM_AL + off) = lp;
                    }
                }
            }
        }

        CP_WAIT1();             // V[t] landed (K[t+1] may still fly)
        __syncthreads();        // A visible + V ready

        // ---- AV gemm: Y += A.V' ----
        #pragma unroll
        for (int ks = 0; ks < 4; ++ks) {
            const u32 ko = ks * 32;
            u32 ah0[4], ah1[4], al0[4], al1[4];
            LDSM4(ah0, aaH[0] + ko); LDSM4(ah1, aaH[1] + ko);
            LDSM4(al0, aaL[0] + ko); LDSM4(al1, aaL[1] + ko);
            #pragma unroll
            for (int h = 0; h < 2; ++h) {
                u32 rh[4], rl[4], ih[4], il[4];
                LDSM4(rh, bV[h] + ko);         LDSM4(rl, bV[h] +  9216 + ko);
                LDSM4(ih, bV[h] + 18432 + ko); LDSM4(il, bV[h] + 27648 + ko);
                MMA(yr[0][2*h],   ah0, rh[0], rh[1]); MMA(yr[0][2*h],   ah0, rl[0], rl[1]); MMA(yr[0][2*h],   al0, rh[0], rh[1]);
                MMA(yr[0][2*h+1], ah0, rh[2], rh[3]); MMA(yr[0][2*h+1], ah0, rl[2], rl[3]); MMA(yr[0][2*h+1], al0, rh[2], rh[3]);
                MMA(yr[1][2*h],   ah1, rh[0], rh[1]); MMA(yr[1][2*h],   ah1, rl[0], rl[1]); MMA(yr[1][2*h],   al1, rh[0], rh[1]);
                MMA(yr[1][2*h+1], ah1, rh[2], rh[3]); MMA(yr[1][2*h+1], ah1, rl[2], rl[3]); MMA(yr[1][2*h+1], al1, rh[2], rh[3]);
                MMA(yi[0][2*h],   ah0, ih[0], ih[1]); MMA(yi[0][2*h],   ah0, il[0], il[1]); MMA(yi[0][2*h],   al0, ih[0], ih[1]);
                MMA(yi[0][2*h+1], ah0, ih[2], ih[3]); MMA(yi[0][2*h+1], ah0, il[2], il[3]); MMA(yi[0][2*h+1], al0, ih[2], ih[3]);
                MMA(yi[1][2*h],   ah1, ih[0], ih[1]); MMA(yi[1][2*h],   ah1, il[0], il[1]); MMA(yi[1][2*h],   al1, ih[0], ih[1]);
                MMA(yi[1][2*h+1], ah1, ih[2], ih[3]); MMA(yi[1][2*h+1], ah1, il[2], il[3]); MMA(yi[1][2*h+1], al1, ih[2], ih[3]);
            }
        }

        __syncthreads();        // every warp finished reading V[t]
        if (t + 1 < NTILES) issue_v(smb, b, t + 1);
        CP_COMMIT();
    }

    // ---- Z reduction: quad shuffle + cross-wk via smem ----
    #pragma unroll
    for (int mf = 0; mf < 2; ++mf)
        #pragma unroll
        for (int rr = 0; rr < 2; ++rr) {
            float z = Zp[mf][rr];
            z += __shfl_xor_sync(0xffffffffu, z, 1);
            z += __shfl_xor_sync(0xffffffffu, z, 2);
            if ((lane & 3) == 0) {
                int q = 32 * wq + 16 * mf + 8 * rr + (lane >> 2);
                *(float*)(sm + SM_ZRED + (wk * 128 + q) * 4) = z;
            }
        }
    __syncthreads();

    // ---- output: Y / Z -> [B, Q, V, 2] ----
    #pragma unroll
    for (int mf = 0; mf < 2; ++mf) {
        #pragma unroll
        for (int rr = 0; rr < 2; ++rr) {
            int q = 32 * wq + 16 * mf + 8 * rr + (lane >> 2);
            float zq = *(float*)(sm + SM_ZRED + q * 4)
                     + *(float*)(sm + SM_ZRED + (128 + q) * 4);
            float inv = 1.0f / zq;
            float2* o = (float2*)gout + (size_t)(b * QLEN + q0 + q) * VH;
            #pragma unroll
            for (int nf = 0; nf < 4; ++nf) {
                #pragma unroll
                for (int cc = 0; cc < 2; ++cc) {
                    int v = 32 * wk + 8 * nf + 2 * (lane & 3) + cc;
                    o[v] = make_float2(yr[mf][nf][rr * 2 + cc] * inv,
                                       yi[mf][nf][rr * 2 + cc] * inv);
                }
            }
        }
    }
}

extern "C" void kernel_launch(void* const* d_in, const int* in_sizes, int n_in,
                              void* d_out, int out_size)
{
    const float* q = (const float*)d_in[0];
    const float* k = (const float*)d_in[1];
    const float* v = (const float*)d_in[2];
    float* out = (float*)d_out;

    prep_k_kernel<<<2048, 256>>>(k);
    prep_v_kernel<<<512, 256>>>(v);

    cudaFuncSetAttribute(cdpa_mma_kernel,
                         cudaFuncAttributeMaxDynamicSharedMemorySize, SM_TOTAL);
    dim3 grid(QLEN / TQ, NB);
    cdpa_mma_kernel<<<grid, NT, SM_TOTAL>>>(q, out);
}